// round 7
// baseline (speedup 1.0000x reference)
#include <cuda_runtime.h>
#include <cstdint>

#define HH 64
#define WW 64
#define HW 4096
#define CCH 256
#define NK 33

// Scratch
__device__ float g_G[2u * 256u * 4096u];  // G = Mt @ Fte + u, per batch
__device__ float g_M[256u * 256u];        // Mt[d][c] = sum_o Wg[o,c] Wf[o,d]
__device__ float g_u[256u];               // u[d]     = sum_o bg[o]   Wf[o,d]

// ---------------------------------------------------------------------------
// f32x2 packed helpers (FFMA2 via PTX fma.rn.f32x2)
// ---------------------------------------------------------------------------
__device__ __forceinline__ unsigned long long pack2_bcast(float x) {
  unsigned long long r;
  asm("mov.b64 %0, {%1, %1};" : "=l"(r) : "f"(x));
  return r;
}
__device__ __forceinline__ unsigned long long ffma2(unsigned long long a,
                                                    unsigned long long b,
                                                    unsigned long long c) {
  unsigned long long d;
  asm("fma.rn.f32x2 %0, %1, %2, %3;" : "=l"(d) : "l"(a), "l"(b), "l"(c));
  return d;
}
__device__ __forceinline__ void unpack2(unsigned long long v, float& lo, float& hi) {
  asm("mov.b64 {%0, %1}, %2;" : "=f"(lo), "=f"(hi) : "l"(v));
}

// ---------------------------------------------------------------------------
// Kernel 0: prep, v3. Blocks 0..63: 32x32 tile of Mt. Block 64: u.
// Whole-K smem slabs loaded with 16 independent LDG.128/thread (MLP=16),
// ONE sync, then an uninterrupted 256-step FMA loop. Dynamic smem 73728 B.
// ---------------------------------------------------------------------------
#define PSTR 36
__global__ __launch_bounds__(256) void psla_prep(const float* __restrict__ Wf,
                                                 const float* __restrict__ Wg,
                                                 const float* __restrict__ bg) {
  const int tid = threadIdx.x;
  if (blockIdx.x == 64) {
    // u[d] = sum_o bg[o] * Wf[o][d]  (coalesced over d = tid)
    float s0 = 0.f, s1 = 0.f, s2 = 0.f, s3 = 0.f;
#pragma unroll
    for (int o = 0; o < 256; o += 4) {
      s0 = fmaf(bg[o + 0], Wf[(o + 0) * 256 + tid], s0);
      s1 = fmaf(bg[o + 1], Wf[(o + 1) * 256 + tid], s1);
      s2 = fmaf(bg[o + 2], Wf[(o + 2) * 256 + tid], s2);
      s3 = fmaf(bg[o + 3], Wf[(o + 3) * 256 + tid], s3);
    }
    g_u[tid] = (s0 + s1) + (s2 + s3);
    return;
  }
  extern __shared__ float psm[];
  float (*sg)[PSTR] = (float (*)[PSTR])psm;               // [256 k][32 c]
  float (*sf)[PSTR] = (float (*)[PSTR])(psm + 256 * PSTR);  // [256 k][32 d]

  const int c0 = (blockIdx.x & 7) * 32;
  const int d0 = (blockIdx.x >> 3) * 32;

  // Thread tid owns row k = tid: 8 float4 from each matrix, all independent.
  float4 ga[8], fa[8];
#pragma unroll
  for (int j = 0; j < 8; j++) {
    ga[j] = *(const float4*)(Wg + (size_t)tid * 256 + c0 + 4 * j);
    fa[j] = *(const float4*)(Wf + (size_t)tid * 256 + d0 + 4 * j);
  }
#pragma unroll
  for (int j = 0; j < 8; j++) {
    *(float4*)&sg[tid][4 * j] = ga[j];
    *(float4*)&sf[tid][4 * j] = fa[j];
  }
  __syncthreads();

  const int tc = (tid & 15) * 2, td = (tid >> 4) * 2;
  float a00 = 0.f, a01 = 0.f, a10 = 0.f, a11 = 0.f;
#pragma unroll 8
  for (int kk = 0; kk < 256; kk++) {
    const float2 g2 = *(const float2*)&sg[kk][tc];
    const float2 f2 = *(const float2*)&sf[kk][td];
    a00 = fmaf(f2.x, g2.x, a00);
    a01 = fmaf(f2.x, g2.y, a01);
    a10 = fmaf(f2.y, g2.x, a10);
    a11 = fmaf(f2.y, g2.y, a11);
  }
  // Mt[d][c] = sum_k Wg[k][c] * Wf[k][d]
  g_M[(size_t)(d0 + td + 0) * 256 + c0 + tc + 0] = a00;
  g_M[(size_t)(d0 + td + 0) * 256 + c0 + tc + 1] = a01;
  g_M[(size_t)(d0 + td + 1) * 256 + c0 + tc + 0] = a10;
  g_M[(size_t)(d0 + td + 1) * 256 + c0 + tc + 1] = a11;
}

// ---------------------------------------------------------------------------
// Kernel 1: G = Mt (256x256) @ Fte (256x4096) + u, per batch.
// 128x128 block tile, kc=8, 256 threads, 8x8 microtile, FFMA2 core.
// ---------------------------------------------------------------------------
__global__ __launch_bounds__(256) void psla_gemm(const float* __restrict__ Fte) {
  __shared__ float sA[8][132];
  __shared__ float sB[8][132];

  const int b = blockIdx.y & 1;
  const int o0 = (blockIdx.y >> 1) * 128;
  const float* X = Fte + (size_t)b * CCH * HW;
  float* Go = g_G + (size_t)b * CCH * HW;

  const int p0 = blockIdx.x * 128;
  const int tid = threadIdx.x;
  const int tx = tid & 15, ty = tid >> 4;

  unsigned long long acc2[8][4];
#pragma unroll
  for (int i = 0; i < 8; i++)
#pragma unroll
    for (int j = 0; j < 4; j++) acc2[i][j] = 0ull;

  const int arow = tid >> 1, acg = (tid & 1) * 4;
  const int brow = tid >> 5, bcol = (tid & 31) * 4;

  for (int k0 = 0; k0 < CCH; k0 += 8) {
    float4 av = *(const float4*)(g_M + (size_t)(o0 + arow) * CCH + k0 + acg);
    float4 bv = *(const float4*)(X + (size_t)(k0 + brow) * HW + p0 + bcol);
    __syncthreads();
    sA[acg + 0][arow] = av.x;
    sA[acg + 1][arow] = av.y;
    sA[acg + 2][arow] = av.z;
    sA[acg + 3][arow] = av.w;
    *(float4*)&sB[brow][bcol] = bv;
    __syncthreads();
#pragma unroll
    for (int kk = 0; kk < 8; kk++) {
      float a[8];
      *(float4*)&a[0] = *(const float4*)&sA[kk][ty * 8];
      *(float4*)&a[4] = *(const float4*)&sA[kk][ty * 8 + 4];
      unsigned long long b2[4];
      ulonglong2 bl0 = *(const ulonglong2*)&sB[kk][tx * 8];
      ulonglong2 bl1 = *(const ulonglong2*)&sB[kk][tx * 8 + 4];
      b2[0] = bl0.x; b2[1] = bl0.y; b2[2] = bl1.x; b2[3] = bl1.y;
      unsigned long long a2[8];
#pragma unroll
      for (int i = 0; i < 8; i++) a2[i] = pack2_bcast(a[i]);
#pragma unroll
      for (int i = 0; i < 8; i++)
#pragma unroll
        for (int j = 0; j < 4; j++) acc2[i][j] = ffma2(a2[i], b2[j], acc2[i][j]);
    }
  }

#pragma unroll
  for (int i = 0; i < 8; i++) {
    const int o = o0 + ty * 8 + i;
    const float bvv = g_u[o];
    float r[8];
#pragma unroll
    for (int j = 0; j < 4; j++) unpack2(acc2[i][j], r[2 * j], r[2 * j + 1]);
#pragma unroll
    for (int j = 0; j < 8; j += 4) {
      float4 v;
      v.x = r[j + 0] + bvv;
      v.y = r[j + 1] + bvv;
      v.z = r[j + 2] + bvv;
      v.w = r[j + 3] + bvv;
      *(float4*)(Go + (size_t)o * HW + p0 + tx * 8 + j) = v;
    }
  }
}

// ---------------------------------------------------------------------------
// Kernel 2: sparse local attention (unchanged from R6).
// 8x8 pixel tile, 512 threads, triple-buffered smem halo [3][256][36].
// ---------------------------------------------------------------------------
#define SST 36
#define ABUF (256 * SST)

__device__ __forceinline__ void halo_fetch(const float* __restrict__ P,
                                           int base, int cg0, bool hin,
                                           int haddr, float4* hv) {
#pragma unroll
  for (int j = 0; j < 4; j++) {
    const int c = base + (cg0 + 2 * j) * 4;
    float4 v;
    v.x = hin ? P[(size_t)(c + 0) * HW + haddr] : 0.f;
    v.y = hin ? P[(size_t)(c + 1) * HW + haddr] : 0.f;
    v.z = hin ? P[(size_t)(c + 2) * HW + haddr] : 0.f;
    v.w = hin ? P[(size_t)(c + 3) * HW + haddr] : 0.f;
    hv[j] = v;
  }
}
__device__ __forceinline__ void halo_store(float* bufq, int cg0,
                                           const float4* hv) {
#pragma unroll
  for (int j = 0; j < 4; j++)
    *(float4*)(bufq + (cg0 + 2 * j) * 4) = hv[j];
}

__global__ __launch_bounds__(512) void psla_attn(const float* __restrict__ Ft,
                                                 float* __restrict__ out) {
  extern __shared__ float sm[];
  constexpr int kdx[NK] = {0, -1,-1,-1,0,0,1,1,1, -2,-2,-2,0,0,2,2,2,
                           -3,-3,-3,0,0,3,3,3, -4,-4,-4,0,0,4,4,4};
  constexpr int kdy[NK] = {0, -1,0,1,-1,1,-1,0,1, -2,0,2,-2,2,-2,0,2,
                           -3,0,3,-3,3,-3,0,3, -4,0,4,-4,4,-4,0,4};

  const int b = blockIdx.z;
  const int gx0 = blockIdx.x * 8, gy0 = blockIdx.y * 8;
  const int tid = threadIdx.x;
  const int px = tid >> 3, sub = tid & 7;
  const int lx = px & 7, ly = px >> 3;
  const int gx = gx0 + lx, gy = gy0 + ly;
  const int gp = gy * WW + gx;

  const float* Gb  = g_G + (size_t)b * CCH * HW;
  const float* Ftb = Ft + (size_t)b * CCH * HW;

  const int q   = tid & 255;
  const int cg0 = tid >> 8;  // 0 or 1
  const int hy = gy0 - 4 + (q >> 4);
  const int hx = gx0 - 4 + (q & 15);
  const bool hin = ((unsigned)hy < HH) && ((unsigned)hx < WW);
  const int haddr = hy * WW + hx;
  float* const myq0 = sm + q * SST;

  const float* const cbase = sm + ((ly + 4) * 16 + (lx + 4)) * SST + sub * 4;

  unsigned long long vmask = 0ull;
#pragma unroll
  for (int k = 0; k < NK; k++)
    if ((unsigned)(gy + kdx[k]) < HH && (unsigned)(gx + kdy[k]) < WW)
      vmask |= (1ull << k);

  float aff[NK];
#pragma unroll
  for (int k = 0; k < NK; k++) aff[k] = 0.f;

  float4 h[2][4];
  float e[3][4];

  // ==== Phase A: aff[k] = <G(p), Ft(p+delta_k)> ====
  halo_fetch(Ftb, 0, cg0, hin, haddr, h[0]);
#pragma unroll
  for (int cc = 0; cc < 4; cc++) e[0][cc] = Gb[(size_t)(sub * 4 + cc) * HW + gp];
  halo_fetch(Ftb, 32, cg0, hin, haddr, h[1]);
#pragma unroll
  for (int cc = 0; cc < 4; cc++)
    e[1][cc] = Gb[(size_t)(32 + sub * 4 + cc) * HW + gp];
  halo_store(myq0, cg0, h[0]);  // buf 0 <- chunk 0
  __syncthreads();

#pragma unroll
  for (int c0 = 0; c0 < 8; c0++) {
    if (c0 < 6) {
      const int base = (c0 + 2) * 32;
      halo_fetch(Ftb, base, cg0, hin, haddr, h[c0 & 1]);
#pragma unroll
      for (int cc = 0; cc < 4; cc++)
        e[(c0 + 2) % 3][cc] = Gb[(size_t)(base + sub * 4 + cc) * HW + gp];
    }
    const float* bp = cbase + (c0 % 3) * ABUF;
    const float e0 = e[c0 % 3][0], e1 = e[c0 % 3][1];
    const float e2 = e[c0 % 3][2], e3 = e[c0 % 3][3];
#pragma unroll
    for (int k = 0; k < NK; k++) {
      const float4 v = *(const float4*)(bp + (kdx[k] * 16 + kdy[k]) * SST);
      float s = fmaf(e0, v.x, 0.f);
      s = fmaf(e1, v.y, s);
      s = fmaf(e2, v.z, s);
      s = fmaf(e3, v.w, s);
      aff[k] += s;
    }
    if (c0 < 7)
      halo_store(myq0 + ((c0 + 1) % 3) * ABUF, cg0, h[(c0 + 1) & 1]);
    __syncthreads();
  }

  // Reduce partial dots across the 8 channel-subgroups (lanes xor 1,2,4).
#pragma unroll
  for (int k = 0; k < NK; k++) {
    aff[k] += __shfl_xor_sync(0xffffffffu, aff[k], 1);
    aff[k] += __shfl_xor_sync(0xffffffffu, aff[k], 2);
    aff[k] += __shfl_xor_sync(0xffffffffu, aff[k], 4);
  }

  // ==== Softmax over valid offsets (k=0 always valid) ====
  float m = aff[0];
#pragma unroll
  for (int k = 1; k < NK; k++)
    if ((vmask >> k) & 1ull) m = fmaxf(m, aff[k]);
  float ssum = 0.f;
#pragma unroll
  for (int k = 0; k < NK; k++) {
    if ((vmask >> k) & 1ull) {
      aff[k] = __expf(aff[k] - m);
      ssum += aff[k];
    } else {
      aff[k] = 0.f;
    }
  }
  const float inv = 1.f / ssum;
#pragma unroll
  for (int k = 0; k < NK; k++) aff[k] *= inv;

  // ==== Phase B: out(c,p) = sum_k w_k * Ft(c, p + delta_k) ====
  halo_fetch(Ftb, 0, cg0, hin, haddr, h[0]);
  halo_fetch(Ftb, 32, cg0, hin, haddr, h[1]);
  halo_store(myq0, cg0, h[0]);
  __syncthreads();

#pragma unroll
  for (int c0 = 0; c0 < 8; c0++) {
    if (c0 < 6)
      halo_fetch(Ftb, (c0 + 2) * 32, cg0, hin, haddr, h[c0 & 1]);

    const float* bp = cbase + (c0 % 3) * ABUF;
    float acc[4] = {0.f, 0.f, 0.f, 0.f};
#pragma unroll
    for (int k = 0; k < NK; k++) {
      const float4 v = *(const float4*)(bp + (kdx[k] * 16 + kdy[k]) * SST);
      const float wk = aff[k];
      acc[0] = fmaf(wk, v.x, acc[0]);
      acc[1] = fmaf(wk, v.y, acc[1]);
      acc[2] = fmaf(wk, v.z, acc[2]);
      acc[3] = fmaf(wk, v.w, acc[3]);
    }
#pragma unroll
    for (int cc = 0; cc < 4; cc++)
      out[(size_t)(b * CCH + c0 * 32 + sub * 4 + cc) * HW + gp] = acc[cc];

    if (c0 < 7)
      halo_store(myq0 + ((c0 + 1) % 3) * ABUF, cg0, h[(c0 + 1) & 1]);
    __syncthreads();
  }
}

// ---------------------------------------------------------------------------
extern "C" void kernel_launch(void* const* d_in, const int* in_sizes, int n_in,
                              void* d_out, int out_size) {
  const float* Ft  = (const float*)d_in[0];
  const float* Fte = (const float*)d_in[1];
  const float* Wf  = (const float*)d_in[2];
  // d_in[3] = bf: cancels in the softmax (constant in k) — unused.
  const float* Wg  = (const float*)d_in[4];
  const float* bg  = (const float*)d_in[5];
  float* out = (float*)d_out;

  const int prep_smem = 2 * 256 * PSTR * (int)sizeof(float);  // 73728 B
  cudaFuncSetAttribute(psla_prep, cudaFuncAttributeMaxDynamicSharedMemorySize,
                       prep_smem);
  const int attn_smem = 3 * ABUF * (int)sizeof(float);  // 110592 B
  cudaFuncSetAttribute(psla_attn, cudaFuncAttributeMaxDynamicSharedMemorySize,
                       attn_smem);

  psla_prep<<<65, 256, prep_smem>>>(Wf, Wg, bg);

  dim3 gg(32, 4);  // p-tiles, (o-tile * 2 + batch)
  psla_gemm<<<gg, 256>>>(Fte);

  dim3 ga(8, 8, 2);  // W/8, H/8, B
  psla_attn<<<ga, 512, attn_smem>>>(Ft, out);
}

// round 8
// speedup vs baseline: 1.0449x; 1.0449x over previous
#include <cuda_runtime.h>
#include <cstdint>

#define HH 64
#define WW 64
#define HW 4096
#define CCH 256
#define NK 33

// Scratch
__device__ float g_G[2u * 256u * 4096u];  // G = Mt @ Fte + u, per batch
__device__ float g_M[256u * 256u];        // Mt[d][c] = sum_o Wg[o,c] Wf[o,d]
__device__ float g_u[256u];               // u[d]     = sum_o bg[o]   Wf[o,d]
__device__ unsigned g_gate = 0u;          // prep-done counter (reset each run)
__device__ unsigned g_done = 0u;          // CTA-done counter  (reset each run)

// ---------------------------------------------------------------------------
// f32x2 packed helpers (FFMA2 via PTX fma.rn.f32x2)
// ---------------------------------------------------------------------------
__device__ __forceinline__ unsigned long long pack2_bcast(float x) {
  unsigned long long r;
  asm("mov.b64 %0, {%1, %1};" : "=l"(r) : "f"(x));
  return r;
}
__device__ __forceinline__ unsigned long long ffma2(unsigned long long a,
                                                    unsigned long long b,
                                                    unsigned long long c) {
  unsigned long long d;
  asm("fma.rn.f32x2 %0, %1, %2, %3;" : "=l"(d) : "l"(a), "l"(b), "l"(c));
  return d;
}
__device__ __forceinline__ void unpack2(unsigned long long v, float& lo, float& hi) {
  asm("mov.b64 {%0, %1}, %2;" : "=f"(lo), "=f"(hi) : "l"(v));
}

// ---------------------------------------------------------------------------
// Kernel 1 (fused): prep (Mt, u) + G = Mt @ Fte + u.
// grid = 128 CTAs (one wave, all co-resident -> spin-gate is deadlock-free).
//   CTA 0..63 : compute 32x32 Mt tile, then its GEMM tile.
//   CTA 64    : compute u, then its GEMM tile.
//   CTA 65..127: wait at gate, then GEMM tile.
// GEMM tile mapping: p0 = (bid&31)*128; y = bid>>5; b = y&1; o0 = (y>>1)*128.
// ---------------------------------------------------------------------------
#define PSTR 36
#define FUSED_SMEM (2 * 256 * PSTR * (int)sizeof(float))  // 73728 B

__global__ __launch_bounds__(256) void psla_gemm_fused(
    const float* __restrict__ Fte, const float* __restrict__ Wf,
    const float* __restrict__ Wg, const float* __restrict__ bg) {
  extern __shared__ float dsm[];
  const int bid = blockIdx.x;
  const int tid = threadIdx.x;

  // ===== Phase 0: prep (first 65 CTAs) =====
  if (bid < 64) {
    float (*sg)[PSTR] = (float (*)[PSTR])dsm;                // [256 k][32 c]
    float (*sf)[PSTR] = (float (*)[PSTR])(dsm + 256 * PSTR); // [256 k][32 d]
    const int c0 = (bid & 7) * 32;
    const int d0 = (bid >> 3) * 32;

    float4 ga[8], fa[8];
#pragma unroll
    for (int j = 0; j < 8; j++) {
      ga[j] = *(const float4*)(Wg + (size_t)tid * 256 + c0 + 4 * j);
      fa[j] = *(const float4*)(Wf + (size_t)tid * 256 + d0 + 4 * j);
    }
#pragma unroll
    for (int j = 0; j < 8; j++) {
      *(float4*)&sg[tid][4 * j] = ga[j];
      *(float4*)&sf[tid][4 * j] = fa[j];
    }
    __syncthreads();

    const int tc = (tid & 15) * 2, td = (tid >> 4) * 2;
    float a00 = 0.f, a01 = 0.f, a10 = 0.f, a11 = 0.f;
#pragma unroll 8
    for (int kk = 0; kk < 256; kk++) {
      const float2 g2 = *(const float2*)&sg[kk][tc];
      const float2 f2 = *(const float2*)&sf[kk][td];
      a00 = fmaf(f2.x, g2.x, a00);
      a01 = fmaf(f2.x, g2.y, a01);
      a10 = fmaf(f2.y, g2.x, a10);
      a11 = fmaf(f2.y, g2.y, a11);
    }
    g_M[(size_t)(d0 + td + 0) * 256 + c0 + tc + 0] = a00;
    g_M[(size_t)(d0 + td + 0) * 256 + c0 + tc + 1] = a01;
    g_M[(size_t)(d0 + td + 1) * 256 + c0 + tc + 0] = a10;
    g_M[(size_t)(d0 + td + 1) * 256 + c0 + tc + 1] = a11;

    __threadfence();
    __syncthreads();
    if (tid == 0) atomicAdd(&g_gate, 1u);
  } else if (bid == 64) {
    // u[d] = sum_o bg[o] * Wf[o][d]
    float s0 = 0.f, s1 = 0.f, s2 = 0.f, s3 = 0.f;
#pragma unroll
    for (int o = 0; o < 256; o += 4) {
      s0 = fmaf(bg[o + 0], Wf[(o + 0) * 256 + tid], s0);
      s1 = fmaf(bg[o + 1], Wf[(o + 1) * 256 + tid], s1);
      s2 = fmaf(bg[o + 2], Wf[(o + 2) * 256 + tid], s2);
      s3 = fmaf(bg[o + 3], Wf[(o + 3) * 256 + tid], s3);
    }
    g_u[tid] = (s0 + s1) + (s2 + s3);
    __threadfence();
    __syncthreads();
    if (tid == 0) atomicAdd(&g_gate, 1u);
  }

  // ===== Gate: wait until all 65 prep pieces are published =====
  if (tid == 0) {
    while (atomicAdd(&g_gate, 0u) < 65u) __nanosleep(64);
  }
  __syncthreads();  // releases CTA; also guards smem reuse below

  // ===== Phase 1: GEMM tile =====
  {
    float* sA = dsm;             // [8][132]
    float* sB = dsm + 8 * 132;   // [8][132]

    const int yy = bid >> 5;
    const int b = yy & 1;
    const int o0 = (yy >> 1) * 128;
    const int p0 = (bid & 31) * 128;
    const float* X = Fte + (size_t)b * CCH * HW;
    float* Go = g_G + (size_t)b * CCH * HW;

    const int tx = tid & 15, ty = tid >> 4;

    unsigned long long acc2[8][4];
#pragma unroll
    for (int i = 0; i < 8; i++)
#pragma unroll
      for (int j = 0; j < 4; j++) acc2[i][j] = 0ull;

    const int arow = tid >> 1, acg = (tid & 1) * 4;
    const int brow = tid >> 5, bcol = (tid & 31) * 4;

    for (int k0 = 0; k0 < CCH; k0 += 8) {
      float4 av = *(const float4*)(g_M + (size_t)(o0 + arow) * CCH + k0 + acg);
      float4 bv = *(const float4*)(X + (size_t)(k0 + brow) * HW + p0 + bcol);
      __syncthreads();
      sA[(acg + 0) * 132 + arow] = av.x;
      sA[(acg + 1) * 132 + arow] = av.y;
      sA[(acg + 2) * 132 + arow] = av.z;
      sA[(acg + 3) * 132 + arow] = av.w;
      *(float4*)&sB[brow * 132 + bcol] = bv;
      __syncthreads();
#pragma unroll
      for (int kk = 0; kk < 8; kk++) {
        float a[8];
        *(float4*)&a[0] = *(const float4*)&sA[kk * 132 + ty * 8];
        *(float4*)&a[4] = *(const float4*)&sA[kk * 132 + ty * 8 + 4];
        unsigned long long b2[4];
        ulonglong2 bl0 = *(const ulonglong2*)&sB[kk * 132 + tx * 8];
        ulonglong2 bl1 = *(const ulonglong2*)&sB[kk * 132 + tx * 8 + 4];
        b2[0] = bl0.x; b2[1] = bl0.y; b2[2] = bl1.x; b2[3] = bl1.y;
        unsigned long long a2[8];
#pragma unroll
        for (int i = 0; i < 8; i++) a2[i] = pack2_bcast(a[i]);
#pragma unroll
        for (int i = 0; i < 8; i++)
#pragma unroll
          for (int j = 0; j < 4; j++)
            acc2[i][j] = ffma2(a2[i], b2[j], acc2[i][j]);
      }
    }

#pragma unroll
    for (int i = 0; i < 8; i++) {
      const int o = o0 + ty * 8 + i;
      const float bvv = g_u[o];
      float r[8];
#pragma unroll
      for (int j = 0; j < 4; j++) unpack2(acc2[i][j], r[2 * j], r[2 * j + 1]);
#pragma unroll
      for (int j = 0; j < 8; j += 4) {
        float4 v;
        v.x = r[j + 0] + bvv;
        v.y = r[j + 1] + bvv;
        v.z = r[j + 2] + bvv;
        v.w = r[j + 3] + bvv;
        *(float4*)(Go + (size_t)o * HW + p0 + tx * 8 + j) = v;
      }
    }
  }

  // ===== Reset counters for the next graph replay (last CTA only) =====
  __syncthreads();
  if (tid == 0) {
    const unsigned d = atomicAdd(&g_done, 1u);
    if (d == 127u) {
      atomicExch(&g_gate, 0u);
      atomicExch(&g_done, 0u);
    }
  }
}

// ---------------------------------------------------------------------------
// Kernel 2: sparse local attention (unchanged from R6/R7).
// 8x8 pixel tile, 512 threads, triple-buffered smem halo [3][256][36].
// ---------------------------------------------------------------------------
#define SST 36
#define ABUF (256 * SST)

__device__ __forceinline__ void halo_fetch(const float* __restrict__ P,
                                           int base, int cg0, bool hin,
                                           int haddr, float4* hv) {
#pragma unroll
  for (int j = 0; j < 4; j++) {
    const int c = base + (cg0 + 2 * j) * 4;
    float4 v;
    v.x = hin ? P[(size_t)(c + 0) * HW + haddr] : 0.f;
    v.y = hin ? P[(size_t)(c + 1) * HW + haddr] : 0.f;
    v.z = hin ? P[(size_t)(c + 2) * HW + haddr] : 0.f;
    v.w = hin ? P[(size_t)(c + 3) * HW + haddr] : 0.f;
    hv[j] = v;
  }
}
__device__ __forceinline__ void halo_store(float* bufq, int cg0,
                                           const float4* hv) {
#pragma unroll
  for (int j = 0; j < 4; j++)
    *(float4*)(bufq + (cg0 + 2 * j) * 4) = hv[j];
}

__global__ __launch_bounds__(512) void psla_attn(const float* __restrict__ Ft,
                                                 float* __restrict__ out) {
  extern __shared__ float sm[];
  constexpr int kdx[NK] = {0, -1,-1,-1,0,0,1,1,1, -2,-2,-2,0,0,2,2,2,
                           -3,-3,-3,0,0,3,3,3, -4,-4,-4,0,0,4,4,4};
  constexpr int kdy[NK] = {0, -1,0,1,-1,1,-1,0,1, -2,0,2,-2,2,-2,0,2,
                           -3,0,3,-3,3,-3,0,3, -4,0,4,-4,4,-4,0,4};

  const int b = blockIdx.z;
  const int gx0 = blockIdx.x * 8, gy0 = blockIdx.y * 8;
  const int tid = threadIdx.x;
  const int px = tid >> 3, sub = tid & 7;
  const int lx = px & 7, ly = px >> 3;
  const int gx = gx0 + lx, gy = gy0 + ly;
  const int gp = gy * WW + gx;

  const float* Gb  = g_G + (size_t)b * CCH * HW;
  const float* Ftb = Ft + (size_t)b * CCH * HW;

  const int q   = tid & 255;
  const int cg0 = tid >> 8;  // 0 or 1
  const int hy = gy0 - 4 + (q >> 4);
  const int hx = gx0 - 4 + (q & 15);
  const bool hin = ((unsigned)hy < HH) && ((unsigned)hx < WW);
  const int haddr = hy * WW + hx;
  float* const myq0 = sm + q * SST;

  const float* const cbase = sm + ((ly + 4) * 16 + (lx + 4)) * SST + sub * 4;

  unsigned long long vmask = 0ull;
#pragma unroll
  for (int k = 0; k < NK; k++)
    if ((unsigned)(gy + kdx[k]) < HH && (unsigned)(gx + kdy[k]) < WW)
      vmask |= (1ull << k);

  float aff[NK];
#pragma unroll
  for (int k = 0; k < NK; k++) aff[k] = 0.f;

  float4 h[2][4];
  float e[3][4];

  // ==== Phase A: aff[k] = <G(p), Ft(p+delta_k)> ====
  halo_fetch(Ftb, 0, cg0, hin, haddr, h[0]);
#pragma unroll
  for (int cc = 0; cc < 4; cc++) e[0][cc] = Gb[(size_t)(sub * 4 + cc) * HW + gp];
  halo_fetch(Ftb, 32, cg0, hin, haddr, h[1]);
#pragma unroll
  for (int cc = 0; cc < 4; cc++)
    e[1][cc] = Gb[(size_t)(32 + sub * 4 + cc) * HW + gp];
  halo_store(myq0, cg0, h[0]);  // buf 0 <- chunk 0
  __syncthreads();

#pragma unroll
  for (int c0 = 0; c0 < 8; c0++) {
    if (c0 < 6) {
      const int base = (c0 + 2) * 32;
      halo_fetch(Ftb, base, cg0, hin, haddr, h[c0 & 1]);
#pragma unroll
      for (int cc = 0; cc < 4; cc++)
        e[(c0 + 2) % 3][cc] = Gb[(size_t)(base + sub * 4 + cc) * HW + gp];
    }
    const float* bp = cbase + (c0 % 3) * ABUF;
    const float e0 = e[c0 % 3][0], e1 = e[c0 % 3][1];
    const float e2 = e[c0 % 3][2], e3 = e[c0 % 3][3];
#pragma unroll
    for (int k = 0; k < NK; k++) {
      const float4 v = *(const float4*)(bp + (kdx[k] * 16 + kdy[k]) * SST);
      float s = fmaf(e0, v.x, 0.f);
      s = fmaf(e1, v.y, s);
      s = fmaf(e2, v.z, s);
      s = fmaf(e3, v.w, s);
      aff[k] += s;
    }
    if (c0 < 7)
      halo_store(myq0 + ((c0 + 1) % 3) * ABUF, cg0, h[(c0 + 1) & 1]);
    __syncthreads();
  }

  // Reduce partial dots across the 8 channel-subgroups (lanes xor 1,2,4).
#pragma unroll
  for (int k = 0; k < NK; k++) {
    aff[k] += __shfl_xor_sync(0xffffffffu, aff[k], 1);
    aff[k] += __shfl_xor_sync(0xffffffffu, aff[k], 2);
    aff[k] += __shfl_xor_sync(0xffffffffu, aff[k], 4);
  }

  // ==== Softmax over valid offsets (k=0 always valid) ====
  float m = aff[0];
#pragma unroll
  for (int k = 1; k < NK; k++)
    if ((vmask >> k) & 1ull) m = fmaxf(m, aff[k]);
  float ssum = 0.f;
#pragma unroll
  for (int k = 0; k < NK; k++) {
    if ((vmask >> k) & 1ull) {
      aff[k] = __expf(aff[k] - m);
      ssum += aff[k];
    } else {
      aff[k] = 0.f;
    }
  }
  const float inv = 1.f / ssum;
#pragma unroll
  for (int k = 0; k < NK; k++) aff[k] *= inv;

  // ==== Phase B: out(c,p) = sum_k w_k * Ft(c, p + delta_k) ====
  halo_fetch(Ftb, 0, cg0, hin, haddr, h[0]);
  halo_fetch(Ftb, 32, cg0, hin, haddr, h[1]);
  halo_store(myq0, cg0, h[0]);
  __syncthreads();

#pragma unroll
  for (int c0 = 0; c0 < 8; c0++) {
    if (c0 < 6)
      halo_fetch(Ftb, (c0 + 2) * 32, cg0, hin, haddr, h[c0 & 1]);

    const float* bp = cbase + (c0 % 3) * ABUF;
    float acc[4] = {0.f, 0.f, 0.f, 0.f};
#pragma unroll
    for (int k = 0; k < NK; k++) {
      const float4 v = *(const float4*)(bp + (kdx[k] * 16 + kdy[k]) * SST);
      const float wk = aff[k];
      acc[0] = fmaf(wk, v.x, acc[0]);
      acc[1] = fmaf(wk, v.y, acc[1]);
      acc[2] = fmaf(wk, v.z, acc[2]);
      acc[3] = fmaf(wk, v.w, acc[3]);
    }
#pragma unroll
    for (int cc = 0; cc < 4; cc++)
      out[(size_t)(b * CCH + c0 * 32 + sub * 4 + cc) * HW + gp] = acc[cc];

    if (c0 < 7)
      halo_store(myq0 + ((c0 + 1) % 3) * ABUF, cg0, h[(c0 + 1) & 1]);
    __syncthreads();
  }
}

// ---------------------------------------------------------------------------
extern "C" void kernel_launch(void* const* d_in, const int* in_sizes, int n_in,
                              void* d_out, int out_size) {
  const float* Ft  = (const float*)d_in[0];
  const float* Fte = (const float*)d_in[1];
  const float* Wf  = (const float*)d_in[2];
  // d_in[3] = bf: cancels in the softmax (constant in k) — unused.
  const float* Wg  = (const float*)d_in[4];
  const float* bg  = (const float*)d_in[5];
  float* out = (float*)d_out;

  cudaFuncSetAttribute(psla_gemm_fused,
                       cudaFuncAttributeMaxDynamicSharedMemorySize, FUSED_SMEM);
  const int attn_smem = 3 * ABUF * (int)sizeof(float);  // 110592 B
  cudaFuncSetAttribute(psla_attn, cudaFuncAttributeMaxDynamicSharedMemorySize,
                       attn_smem);

  psla_gemm_fused<<<128, 256, FUSED_SMEM>>>(Fte, Wf, Wg, bg);

  dim3 ga(8, 8, 2);  // W/8, H/8, B
  psla_attn<<<ga, 512, attn_smem>>>(Ft, out);
}